// round 6
// baseline (speedup 1.0000x reference)
#include <cuda_runtime.h>
#include <cuda_bf16.h>
#include <stdint.h>

#define SEQ 4096
#define DM  1024
#define NHEAD 16
#define HD 64

// ---------------- device scratch ----------------
__device__ uint16_t g_Xh[SEQ*DM], g_Xl[SEQ*DM];          // X bf16 hi/lo
__device__ uint16_t g_Wth[4*DM*DM], g_Wtl[4*DM*DM];      // W^T bf16 hi/lo [n][k]
__device__ uint32_t g_Qf[SEQ*DM], g_Kf[SEQ*DM];          // tf32 (Q pre-scaled 0.125)
__device__ float    g_V[SEQ*DM];
__device__ uint16_t g_Vth[SEQ*DM], g_Vtl[SEQ*DM];        // V transposed: [c][j]
__device__ uint16_t g_Ah[SEQ*DM], g_Al[SEQ*DM];          // attn out bf16 hi/lo

// ---------------- helpers ----------------
__device__ __forceinline__ uint32_t f2tf(float x){
    uint32_t r; asm("cvt.rna.tf32.f32 %0, %1;" : "=r"(r) : "f"(x)); return r;
}
__device__ __forceinline__ void split2b(float v, uint16_t& h, uint16_t& l){
    __nv_bfloat16 bh = __float2bfloat16(v);
    h = __bfloat16_as_ushort(bh);
    l = __bfloat16_as_ushort(__float2bfloat16(v - __bfloat162float(bh)));
}
__device__ __forceinline__ void mma8(float* c, const uint32_t* a, const uint32_t* b){
    asm volatile(
        "mma.sync.aligned.m16n8k8.row.col.f32.tf32.tf32.f32 "
        "{%0,%1,%2,%3}, {%4,%5,%6,%7}, {%8,%9}, {%0,%1,%2,%3};"
        : "+f"(c[0]), "+f"(c[1]), "+f"(c[2]), "+f"(c[3])
        : "r"(a[0]), "r"(a[1]), "r"(a[2]), "r"(a[3]), "r"(b[0]), "r"(b[1]));
}
__device__ __forceinline__ void mma16(float* c, const uint32_t* a, const uint32_t* b){
    asm volatile(
        "mma.sync.aligned.m16n8k16.row.col.f32.bf16.bf16.f32 "
        "{%0,%1,%2,%3}, {%4,%5,%6,%7}, {%8,%9}, {%0,%1,%2,%3};"
        : "+f"(c[0]), "+f"(c[1]), "+f"(c[2]), "+f"(c[3])
        : "r"(a[0]), "r"(a[1]), "r"(a[2]), "r"(a[3]), "r"(b[0]), "r"(b[1]));
}
__device__ __forceinline__ void ldsm4(uint32_t* r, uint32_t addr){
    asm volatile("ldmatrix.sync.aligned.m8n8.x4.shared.b16 {%0,%1,%2,%3}, [%4];"
        : "=r"(r[0]), "=r"(r[1]), "=r"(r[2]), "=r"(r[3]) : "r"(addr));
}
__device__ __forceinline__ void cpa16(uint32_t dst, const void* src){
    asm volatile("cp.async.cg.shared.global [%0], [%1], 16;" :: "r"(dst), "l"(src));
}
#define CPCOMMIT asm volatile("cp.async.commit_group;")
template<int N> __device__ __forceinline__ void cpwait(){
    asm volatile("cp.async.wait_group %0;" :: "n"(N));
}

// ---------------- setup kernels ----------------
__global__ void split_x_kernel(const float* __restrict__ X){
    int i = (blockIdx.x * 256 + threadIdx.x) * 4;
    float4 v = *(const float4*)(X + i);
    uint16_t h0,l0,h1,l1,h2,l2,h3,l3;
    split2b(v.x,h0,l0); split2b(v.y,h1,l1); split2b(v.z,h2,l2); split2b(v.w,h3,l3);
    ((uint32_t*)g_Xh)[i/2]   = (uint32_t)h0 | ((uint32_t)h1 << 16);
    ((uint32_t*)g_Xh)[i/2+1] = (uint32_t)h2 | ((uint32_t)h3 << 16);
    ((uint32_t*)g_Xl)[i/2]   = (uint32_t)l0 | ((uint32_t)l1 << 16);
    ((uint32_t*)g_Xl)[i/2+1] = (uint32_t)l2 | ((uint32_t)l3 << 16);
}

__global__ void splitT_w_kernel(const float* __restrict__ W0, const float* __restrict__ W1,
                                const float* __restrict__ W2, const float* __restrict__ W3){
    __shared__ float tile[32][33];
    int z = blockIdx.z;
    const float* W = (z==0)?W0:(z==1)?W1:(z==2)?W2:W3;
    uint16_t* oh = g_Wth + (size_t)z * DM * DM;
    uint16_t* ol = g_Wtl + (size_t)z * DM * DM;
    int tx = threadIdx.x, ty = threadIdx.y;
    int x = blockIdx.x * 32 + tx, y = blockIdx.y * 32 + ty;
#pragma unroll
    for (int i = 0; i < 32; i += 8)
        tile[ty + i][tx] = W[(size_t)(y + i) * DM + x];
    __syncthreads();
    int xo = blockIdx.y * 32 + tx, yo = blockIdx.x * 32 + ty;
#pragma unroll
    for (int i = 0; i < 32; i += 8){
        float v = tile[tx][ty + i];
        uint16_t h, l; split2b(v, h, l);
        oh[(size_t)(yo + i) * DM + xo] = h;
        ol[(size_t)(yo + i) * DM + xo] = l;
    }
}

__global__ void vsplitT_kernel(){
    __shared__ float tile[32][33];
    int tx = threadIdx.x, ty = threadIdx.y;
    int x = blockIdx.x * 32 + tx, y = blockIdx.y * 32 + ty;
#pragma unroll
    for (int i = 0; i < 32; i += 8)
        tile[ty + i][tx] = g_V[(size_t)(y + i) * DM + x];
    __syncthreads();
    int c = blockIdx.x * 32 + ty, j = blockIdx.y * 32 + tx;
#pragma unroll
    for (int i = 0; i < 32; i += 8){
        float v = tile[tx][ty + i];
        uint16_t h, l; split2b(v, h, l);
        g_Vth[(size_t)(c + i) * SEQ + j] = h;
        g_Vtl[(size_t)(c + i) * SEQ + j] = l;
    }
}

// ---------------- bf16x3 GEMM core: 128x128 tile, BK=32, 256 thr -------------
#define G_ST   20
#define G_ARR  2560
#define G_OFF(s,a) (((s)*4 + (a)) * G_ARR)
#define G_SMEM_BYTES (2*4*G_ARR*4)

extern __shared__ uint32_t dynsm[];

__device__ __forceinline__ void gemm_core(const uint16_t* __restrict__ Agh,
                                          const uint16_t* __restrict__ Agl,
                                          const uint16_t* __restrict__ Bgh,
                                          const uint16_t* __restrict__ Bgl,
                                          float acc[4][4][4])
{
    const int tid  = threadIdx.x;
    const int lane = tid & 31;
    const int w    = tid >> 5;
    const int wm   = w >> 2, wn = w & 3;
    const int bm   = blockIdx.y, bn = blockIdx.x;
    const uint32_t smb = (uint32_t)__cvta_generic_to_shared(dynsm);

#pragma unroll
    for (int i = 0; i < 4; i++)
#pragma unroll
        for (int j = 0; j < 4; j++)
#pragma unroll
            for (int e = 0; e < 4; e++) acc[i][j][e] = 0.f;

    const int c0row = (2*tid) >> 2, c0off = (2*tid) & 3;
    const int c1row = (2*tid+1) >> 2, c1off = (2*tid+1) & 3;
    const size_t gA0 = (size_t)(bm*128 + c0row) * DM + c0off*8;
    const size_t gA1 = (size_t)(bm*128 + c1row) * DM + c1off*8;
    const size_t gB0 = (size_t)(bn*128 + c0row) * DM + c0off*8;
    const size_t gB1 = (size_t)(bn*128 + c1row) * DM + c1off*8;
    const int s0 = c0row*G_ST*4 + c0off*16;
    const int s1 = c1row*G_ST*4 + c1off*16;

    const int lrow  = (lane & 7) + ((lane >> 3) & 1) * 8;
    const int lcA   = ((lane >> 4) & 1) * 4;
    const int lrowB = (lane & 7) + ((lane >> 4) & 1) * 8;
    const int lcB   = ((lane >> 3) & 1) * 4;
    int aoff[4], boff[2];
#pragma unroll
    for (int mt = 0; mt < 4; mt++) aoff[mt] = (wm*64 + mt*16 + lrow) * G_ST + lcA;
#pragma unroll
    for (int np = 0; np < 2; np++) boff[np] = (wn*32 + np*16 + lrowB) * G_ST + lcB;

#define G_PREF(s, k0)                                                          \
    do {                                                                       \
        cpa16(smb + G_OFF(s,0)*4 + s0, Agh + gA0 + (k0));                      \
        cpa16(smb + G_OFF(s,0)*4 + s1, Agh + gA1 + (k0));                      \
        cpa16(smb + G_OFF(s,1)*4 + s0, Agl + gA0 + (k0));                      \
        cpa16(smb + G_OFF(s,1)*4 + s1, Agl + gA1 + (k0));                      \
        cpa16(smb + G_OFF(s,2)*4 + s0, Bgh + gB0 + (k0));                      \
        cpa16(smb + G_OFF(s,2)*4 + s1, Bgh + gB1 + (k0));                      \
        cpa16(smb + G_OFF(s,3)*4 + s0, Bgl + gB0 + (k0));                      \
        cpa16(smb + G_OFF(s,3)*4 + s1, Bgl + gB1 + (k0));                      \
        CPCOMMIT;                                                              \
    } while (0)

    G_PREF(0, 0);

    int buf = 0;
    for (int kt = 0; kt < 32; kt++){
        if (kt < 31){
            G_PREF(buf ^ 1, (kt + 1) * 32);
            cpwait<1>();
        } else {
            cpwait<0>();
        }
        __syncthreads();

        const int ah = G_OFF(buf,0), al = G_OFF(buf,1);
        const int bh = G_OFF(buf,2), bl = G_OFF(buf,3);
#pragma unroll
        for (int ks = 0; ks < 2; ks++){
            uint32_t Af[4][4], Alf[4][4], Bf[2][4], Blf[2][4];
#pragma unroll
            for (int mt = 0; mt < 4; mt++){
                ldsm4(Af[mt],  smb + (ah + aoff[mt] + ks*8)*4);
                ldsm4(Alf[mt], smb + (al + aoff[mt] + ks*8)*4);
            }
#pragma unroll
            for (int np = 0; np < 2; np++){
                ldsm4(Bf[np],  smb + (bh + boff[np] + ks*8)*4);
                ldsm4(Blf[np], smb + (bl + boff[np] + ks*8)*4);
            }
#pragma unroll
            for (int mt = 0; mt < 4; mt++)
#pragma unroll
                for (int nt = 0; nt < 4; nt++){
                    const uint32_t* bhp = &Bf [nt>>1][(nt&1)*2];
                    const uint32_t* blp = &Blf[nt>>1][(nt&1)*2];
                    mma16(acc[mt][nt], Af[mt],  bhp);
                    mma16(acc[mt][nt], Af[mt],  blp);
                    mma16(acc[mt][nt], Alf[mt], bhp);
                }
        }
        __syncthreads();
        buf ^= 1;
    }
#undef G_PREF
}

__global__ __launch_bounds__(256)
void gemm_qkv_kernel(){
    float acc[4][4][4];
    const int z = blockIdx.z;
    gemm_core(g_Xh, g_Xl, g_Wth + (size_t)z*DM*DM, g_Wtl + (size_t)z*DM*DM, acc);

    const int tid = threadIdx.x, lane = tid & 31, w = tid >> 5;
    const int g = lane >> 2, t = lane & 3, wm = w >> 2, wn = w & 3;
#pragma unroll
    for (int mt = 0; mt < 4; mt++){
        int r = blockIdx.y*128 + wm*64 + mt*16 + g;
#pragma unroll
        for (int nt = 0; nt < 4; nt++){
            int c = blockIdx.x*128 + wn*32 + nt*8 + 2*t;
            float v0 = acc[mt][nt][0], v1 = acc[mt][nt][1];
            float v2 = acc[mt][nt][2], v3 = acc[mt][nt][3];
            if (z == 2){
                *(float2*)(g_V + (size_t)r*DM + c)     = make_float2(v0, v1);
                *(float2*)(g_V + (size_t)(r+8)*DM + c) = make_float2(v2, v3);
            } else {
                float sc = (z == 0) ? 0.125f : 1.0f;
                uint32_t* dst = (z == 0) ? g_Qf : g_Kf;
                *(uint2*)(dst + (size_t)r*DM + c)     = make_uint2(f2tf(v0*sc), f2tf(v1*sc));
                *(uint2*)(dst + (size_t)(r+8)*DM + c) = make_uint2(f2tf(v2*sc), f2tf(v3*sc));
            }
        }
    }
}

__global__ __launch_bounds__(256)
void gemm_wo_kernel(float* __restrict__ out){
    float acc[4][4][4];
    gemm_core(g_Ah, g_Al, g_Wth + (size_t)3*DM*DM, g_Wtl + (size_t)3*DM*DM, acc);

    const int tid = threadIdx.x, lane = tid & 31, w = tid >> 5;
    const int g = lane >> 2, t = lane & 3, wm = w >> 2, wn = w & 3;
#pragma unroll
    for (int mt = 0; mt < 4; mt++){
        int r = blockIdx.y*128 + wm*64 + mt*16 + g;
#pragma unroll
        for (int nt = 0; nt < 4; nt++){
            int c = blockIdx.x*128 + wn*32 + nt*8 + 2*t;
            *(float2*)(out + (size_t)r*DM + c)     = make_float2(acc[mt][nt][0], acc[mt][nt][1]);
            *(float2*)(out + (size_t)(r+8)*DM + c) = make_float2(acc[mt][nt][2], acc[mt][nt][3]);
        }
    }
}

// ---------------- attention: QK tf32, PV bf16x3, 3-stage pipeline ------------
// K tile (tf32): 32 rows x 68 words, 3 buf. V tile (bf16 h+l): 64 x 20 words, 3 buf.
// Q (tf32) 128 x 68 overlaid by P after consumption.
#define A_KBUF 2176
#define A_OK(b)  ((b)*A_KBUF)            // 3 stages: 0..6528
#define A_VBUF 2560                      // hi(1280)+lo(1280)
#define A_OVH(b) (6528 + (b)*A_VBUF)
#define A_OVL(b) (A_OVH(b) + 1280)
#define A_OPQ    14208
#define A_SMEM_BYTES ((A_OPQ + 128*68)*4)

__global__ __launch_bounds__(256)
void attn_kernel(){
    uint32_t* sm = dynsm;
    const uint32_t smb = (uint32_t)__cvta_generic_to_shared(sm);
    const int tid = threadIdx.x, lane = tid & 31, w = tid >> 5;
    const int g = lane >> 2, t = lane & 3;
    const int h = blockIdx.y;
    // longest-first: high-q0 blocks (most kv tiles) launch first
    const int q0 = (int)(gridDim.x - 1 - blockIdx.x) * 128;

    const int lrow  = (lane & 7) + ((lane >> 3) & 1) * 8;
    const int lcA   = ((lane >> 4) & 1) * 4;
    const int lrowB = (lane & 7) + ((lane >> 4) & 1) * 8;
    const int lcB   = ((lane >> 3) & 1) * 4;

    const int kr = tid >> 4, kc = (tid & 15) * 4;
    const int vrow = tid >> 2, voff = tid & 3;

#define A_PREF_KV(b, j0)                                                          \
    do {                                                                          \
        cpa16(smb + (A_OK(b) + kr*68 + kc)*4,      g_Kf + (size_t)((j0)+kr)*DM + (size_t)h*64 + kc);      \
        cpa16(smb + (A_OK(b) + (kr+16)*68 + kc)*4, g_Kf + (size_t)((j0)+kr+16)*DM + (size_t)h*64 + kc);   \
        cpa16(smb + (A_OVH(b)*4 + vrow*80 + voff*16), g_Vth + (size_t)(h*64+vrow)*SEQ + (j0) + voff*8);   \
        cpa16(smb + (A_OVL(b)*4 + vrow*80 + voff*16), g_Vtl + (size_t)(h*64+vrow)*SEQ + (j0) + voff*8);   \
        CPCOMMIT;                                                                 \
    } while (0)

    const int ntile = q0 / 32 + 4;

    // prologue: stages 0,1 + Q, then drain everything
    A_PREF_KV(0, 0);
    A_PREF_KV(1, 32);
#pragma unroll
    for (int i = 0; i < 8; i++){
        int c = tid + i*256;
        int qr = c >> 4, qc = (c & 15) * 4;
        cpa16(smb + (A_OPQ + qr*68 + qc)*4, g_Qf + (size_t)(q0+qr)*DM + (size_t)h*64 + qc);
    }
    CPCOMMIT;
    cpwait<0>();
    __syncthreads();

    uint32_t qf[8][4];
#pragma unroll
    for (int kcc = 0; kcc < 8; kcc++)
        ldsm4(qf[kcc], smb + (A_OPQ + (w*16 + lrow)*68 + kcc*8 + lcA)*4);
    __syncthreads();       // Q region becomes P region

    float o[8][4];
#pragma unroll
    for (int nd = 0; nd < 8; nd++)
#pragma unroll
        for (int e = 0; e < 4; e++) o[nd][e] = 0.f;
    float m0 = -1e30f, m1 = -1e30f, l0 = 0.f, l1 = 0.f;

    const int r0 = q0 + w*16 + g, r1 = r0 + 8;
    uint32_t* Ph = sm + A_OPQ + w * 640;
    uint32_t* Pl = Ph + 320;
    const uint32_t phb = smb + (A_OPQ + w*640)*4;
    const uint32_t plb = phb + 320*4;

    int st = 0, st2 = 2;   // current stage, prefetch-target stage
    for (int it = 0; it < ntile; it++){
        // one barrier per tile: proves all warps finished the previous tile's
        // reads (so st2 may be overwritten) and makes stage `st` data visible.
        if (it) __syncthreads();
        if (it + 2 < ntile){
            A_PREF_KV(st2, (it + 2) * 32);
            cpwait<2>();
        } else if (it + 1 < ntile){
            cpwait<1>();
        } else {
            cpwait<0>();
        }
        if (!it) __syncthreads();   // first tile: ensure prologue visibility ordering kept

        // S = Q K^T (tf32)
        float s[4][4];
#pragma unroll
        for (int nt = 0; nt < 4; nt++)
#pragma unroll
            for (int e = 0; e < 4; e++) s[nt][e] = 0.f;
#pragma unroll
        for (int kcc = 0; kcc < 8; kcc++){
            uint32_t Bf[2][4];
            ldsm4(Bf[0], smb + (A_OK(st) + lrowB*68      + kcc*8 + lcB)*4);
            ldsm4(Bf[1], smb + (A_OK(st) + (16+lrowB)*68 + kcc*8 + lcB)*4);
#pragma unroll
            for (int nt = 0; nt < 4; nt++)
                mma8(s[nt], qf[kcc], &Bf[nt>>1][(nt&1)*2]);
        }

        const int j0 = it * 32;
        const bool domask = (j0 >= q0);

        float mx0 = -1e30f, mx1 = -1e30f;
#pragma unroll
        for (int nt = 0; nt < 4; nt++){
            int jc = j0 + nt*8 + 2*t;
#pragma unroll
            for (int e = 0; e < 4; e++){
                int j = jc + (e & 1);
                int r = (e < 2) ? r0 : r1;
                float sc = s[nt][e];
                if (domask && j > r) sc = -1e30f;
                s[nt][e] = sc;
                if (e < 2) mx0 = fmaxf(mx0, sc); else mx1 = fmaxf(mx1, sc);
            }
        }
        mx0 = fmaxf(mx0, __shfl_xor_sync(0xffffffffu, mx0, 1));
        mx0 = fmaxf(mx0, __shfl_xor_sync(0xffffffffu, mx0, 2));
        mx1 = fmaxf(mx1, __shfl_xor_sync(0xffffffffu, mx1, 1));
        mx1 = fmaxf(mx1, __shfl_xor_sync(0xffffffffu, mx1, 2));

        float mn0 = fmaxf(m0, mx0), mn1 = fmaxf(m1, mx1);
        float a0 = __expf(m0 - mn0), a1 = __expf(m1 - mn1);
        m0 = mn0; m1 = mn1;
        l0 *= a0;  l1 *= a1;
#pragma unroll
        for (int nd = 0; nd < 8; nd++){
            o[nd][0] *= a0; o[nd][1] *= a0;
            o[nd][2] *= a1; o[nd][3] *= a1;
        }

#pragma unroll
        for (int nt = 0; nt < 4; nt++){
            float p0 = __expf(s[nt][0] - mn0), p1 = __expf(s[nt][1] - mn0);
            float p2 = __expf(s[nt][2] - mn1), p3 = __expf(s[nt][3] - mn1);
            l0 += p0 + p1; l1 += p2 + p3;
            uint16_t h0,lo0,h1,lo1,h2,lo2,h3,lo3;
            split2b(p0,h0,lo0); split2b(p1,h1,lo1);
            split2b(p2,h2,lo2); split2b(p3,h3,lo3);
            int pw = nt*4 + t;
            Ph[g*20 + pw]     = (uint32_t)h0  | ((uint32_t)h1  << 16);
            Ph[(g+8)*20 + pw] = (uint32_t)h2  | ((uint32_t)h3  << 16);
            Pl[g*20 + pw]     = (uint32_t)lo0 | ((uint32_t)lo1 << 16);
            Pl[(g+8)*20 + pw] = (uint32_t)lo2 | ((uint32_t)lo3 << 16);
        }
        __syncwarp();

        // O += P V  (bf16x3, k16)
#pragma unroll
        for (int kt = 0; kt < 2; kt++){
            uint32_t pf[4], plf[4];
            ldsm4(pf,  phb + (lrow*20 + kt*8 + lcA)*4);
            ldsm4(plf, plb + (lrow*20 + kt*8 + lcA)*4);
#pragma unroll
            for (int np = 0; np < 4; np++){
                uint32_t Vf[4], Vlf[4];
                ldsm4(Vf,  smb + (A_OVH(st) + (np*16+lrowB)*20 + kt*8 + lcB)*4);
                ldsm4(Vlf, smb + (A_OVL(st) + (np*16+lrowB)*20 + kt*8 + lcB)*4);
                mma16(o[2*np],   pf,  &Vf[0]);
                mma16(o[2*np],   pf,  &Vlf[0]);
                mma16(o[2*np],   plf, &Vf[0]);
                mma16(o[2*np+1], pf,  &Vf[2]);
                mma16(o[2*np+1], pf,  &Vlf[2]);
                mma16(o[2*np+1], plf, &Vf[2]);
            }
        }
        st  = (st  == 2) ? 0 : st  + 1;
        st2 = (st2 == 2) ? 0 : st2 + 1;
    }
#undef A_PREF_KV

    l0 += __shfl_xor_sync(0xffffffffu, l0, 1);
    l0 += __shfl_xor_sync(0xffffffffu, l0, 2);
    l1 += __shfl_xor_sync(0xffffffffu, l1, 1);
    l1 += __shfl_xor_sync(0xffffffffu, l1, 2);
    float inv0 = 1.f / l0, inv1 = 1.f / l1;

#pragma unroll
    for (int nd = 0; nd < 8; nd++){
        int c = h*64 + nd*8 + 2*t;
        uint16_t h0,lo0,h1,lo1;
        split2b(o[nd][0]*inv0, h0, lo0); split2b(o[nd][1]*inv0, h1, lo1);
        ((uint32_t*)g_Ah)[((size_t)r0*DM + c) >> 1] = (uint32_t)h0  | ((uint32_t)h1 << 16);
        ((uint32_t*)g_Al)[((size_t)r0*DM + c) >> 1] = (uint32_t)lo0 | ((uint32_t)lo1 << 16);
        split2b(o[nd][2]*inv1, h0, lo0); split2b(o[nd][3]*inv1, h1, lo1);
        ((uint32_t*)g_Ah)[((size_t)r1*DM + c) >> 1] = (uint32_t)h0  | ((uint32_t)h1 << 16);
        ((uint32_t*)g_Al)[((size_t)r1*DM + c) >> 1] = (uint32_t)lo0 | ((uint32_t)lo1 << 16);
    }
}

// ---------------- launch ----------------
extern "C" void kernel_launch(void* const* d_in, const int* in_sizes, int n_in,
                              void* d_out, int out_size)
{
    const float* x  = (const float*)d_in[0];
    const float* Wq = (const float*)d_in[1];
    const float* Wk = (const float*)d_in[2];
    const float* Wv = (const float*)d_in[3];
    const float* Wo = (const float*)d_in[4];
    float* out = (float*)d_out;

    cudaFuncSetAttribute(gemm_qkv_kernel, cudaFuncAttributeMaxDynamicSharedMemorySize, G_SMEM_BYTES);
    cudaFuncSetAttribute(gemm_wo_kernel,  cudaFuncAttributeMaxDynamicSharedMemorySize, G_SMEM_BYTES);
    cudaFuncSetAttribute(attn_kernel,     cudaFuncAttributeMaxDynamicSharedMemorySize, A_SMEM_BYTES);

    split_x_kernel<<<SEQ*DM/1024, 256>>>(x);
    splitT_w_kernel<<<dim3(32,32,4), dim3(32,8)>>>(Wq, Wk, Wv, Wo);

    gemm_qkv_kernel<<<dim3(8,32,3), 256, G_SMEM_BYTES>>>();

    vsplitT_kernel<<<dim3(32,128), dim3(32,8)>>>();

    attn_kernel<<<dim3(32,16), 256, A_SMEM_BYTES>>>();

    gemm_wo_kernel<<<dim3(8,32), 256, G_SMEM_BYTES>>>(out);
}

// round 7
// speedup vs baseline: 1.0376x; 1.0376x over previous
#include <cuda_runtime.h>
#include <cuda_bf16.h>
#include <stdint.h>

#define SEQ 4096
#define DM  1024
#define NHEAD 16
#define HD 64

// ---------------- device scratch ----------------
__device__ uint16_t g_Xh[SEQ*DM], g_Xl[SEQ*DM];          // X bf16 hi/lo
__device__ uint16_t g_Wth[4*DM*DM], g_Wtl[4*DM*DM];      // W^T bf16 hi/lo [n][k]
__device__ uint32_t g_Qf[SEQ*DM], g_Kf[SEQ*DM];          // tf32 (Q pre-scaled 0.125*log2e)
__device__ float    g_V[SEQ*DM];
__device__ uint16_t g_Vth[SEQ*DM], g_Vtl[SEQ*DM];        // V transposed: [c][j]
__device__ uint16_t g_Ah[SEQ*DM], g_Al[SEQ*DM];          // attn out bf16 hi/lo

// ---------------- helpers ----------------
__device__ __forceinline__ uint32_t f2tf(float x){
    uint32_t r; asm("cvt.rna.tf32.f32 %0, %1;" : "=r"(r) : "f"(x)); return r;
}
__device__ __forceinline__ float ex2(float x){
    float r; asm("ex2.approx.ftz.f32 %0, %1;" : "=f"(r) : "f"(x)); return r;
}
__device__ __forceinline__ void split2b(float v, uint16_t& h, uint16_t& l){
    __nv_bfloat16 bh = __float2bfloat16(v);
    h = __bfloat16_as_ushort(bh);
    l = __bfloat16_as_ushort(__float2bfloat16(v - __bfloat162float(bh)));
}
__device__ __forceinline__ void mma8(float* c, const uint32_t* a, const uint32_t* b){
    asm volatile(
        "mma.sync.aligned.m16n8k8.row.col.f32.tf32.tf32.f32 "
        "{%0,%1,%2,%3}, {%4,%5,%6,%7}, {%8,%9}, {%0,%1,%2,%3};"
        : "+f"(c[0]), "+f"(c[1]), "+f"(c[2]), "+f"(c[3])
        : "r"(a[0]), "r"(a[1]), "r"(a[2]), "r"(a[3]), "r"(b[0]), "r"(b[1]));
}
__device__ __forceinline__ void mma16(float* c, const uint32_t* a, const uint32_t* b){
    asm volatile(
        "mma.sync.aligned.m16n8k16.row.col.f32.bf16.bf16.f32 "
        "{%0,%1,%2,%3}, {%4,%5,%6,%7}, {%8,%9}, {%0,%1,%2,%3};"
        : "+f"(c[0]), "+f"(c[1]), "+f"(c[2]), "+f"(c[3])
        : "r"(a[0]), "r"(a[1]), "r"(a[2]), "r"(a[3]), "r"(b[0]), "r"(b[1]));
}
__device__ __forceinline__ void ldsm4(uint32_t* r, uint32_t addr){
    asm volatile("ldmatrix.sync.aligned.m8n8.x4.shared.b16 {%0,%1,%2,%3}, [%4];"
        : "=r"(r[0]), "=r"(r[1]), "=r"(r[2]), "=r"(r[3]) : "r"(addr));
}
__device__ __forceinline__ void cpa16(uint32_t dst, const void* src){
    asm volatile("cp.async.cg.shared.global [%0], [%1], 16;" :: "r"(dst), "l"(src));
}
#define CPCOMMIT asm volatile("cp.async.commit_group;")
template<int N> __device__ __forceinline__ void cpwait(){
    asm volatile("cp.async.wait_group %0;" :: "n"(N));
}

// ---------------- setup kernels ----------------
__global__ void split_x_kernel(const float* __restrict__ X){
    int i = (blockIdx.x * 256 + threadIdx.x) * 4;
    float4 v = *(const float4*)(X + i);
    uint16_t h0,l0,h1,l1,h2,l2,h3,l3;
    split2b(v.x,h0,l0); split2b(v.y,h1,l1); split2b(v.z,h2,l2); split2b(v.w,h3,l3);
    ((uint32_t*)g_Xh)[i/2]   = (uint32_t)h0 | ((uint32_t)h1 << 16);
    ((uint32_t*)g_Xh)[i/2+1] = (uint32_t)h2 | ((uint32_t)h3 << 16);
    ((uint32_t*)g_Xl)[i/2]   = (uint32_t)l0 | ((uint32_t)l1 << 16);
    ((uint32_t*)g_Xl)[i/2+1] = (uint32_t)l2 | ((uint32_t)l3 << 16);
}

__global__ void splitT_w_kernel(const float* __restrict__ W0, const float* __restrict__ W1,
                                const float* __restrict__ W2, const float* __restrict__ W3){
    __shared__ float tile[32][33];
    int z = blockIdx.z;
    const float* W = (z==0)?W0:(z==1)?W1:(z==2)?W2:W3;
    uint16_t* oh = g_Wth + (size_t)z * DM * DM;
    uint16_t* ol = g_Wtl + (size_t)z * DM * DM;
    int tx = threadIdx.x, ty = threadIdx.y;
    int x = blockIdx.x * 32 + tx, y = blockIdx.y * 32 + ty;
#pragma unroll
    for (int i = 0; i < 32; i += 8)
        tile[ty + i][tx] = W[(size_t)(y + i) * DM + x];
    __syncthreads();
    int xo = blockIdx.y * 32 + tx, yo = blockIdx.x * 32 + ty;
#pragma unroll
    for (int i = 0; i < 32; i += 8){
        float v = tile[tx][ty + i];
        uint16_t h, l; split2b(v, h, l);
        oh[(size_t)(yo + i) * DM + xo] = h;
        ol[(size_t)(yo + i) * DM + xo] = l;
    }
}

__global__ void vsplitT_kernel(){
    __shared__ float tile[32][33];
    int tx = threadIdx.x, ty = threadIdx.y;
    int x = blockIdx.x * 32 + tx, y = blockIdx.y * 32 + ty;
#pragma unroll
    for (int i = 0; i < 32; i += 8)
        tile[ty + i][tx] = g_V[(size_t)(y + i) * DM + x];
    __syncthreads();
    int c = blockIdx.x * 32 + ty, j = blockIdx.y * 32 + tx;
#pragma unroll
    for (int i = 0; i < 32; i += 8){
        float v = tile[tx][ty + i];
        uint16_t h, l; split2b(v, h, l);
        g_Vth[(size_t)(c + i) * SEQ + j] = h;
        g_Vtl[(size_t)(c + i) * SEQ + j] = l;
    }
}

// ---------------- bf16x3 GEMM core: 128x128 tile, BK=32, 256 thr -------------
#define G_ST   20
#define G_ARR  2560
#define G_OFF(s,a) (((s)*4 + (a)) * G_ARR)
#define G_SMEM_BYTES (2*4*G_ARR*4)

extern __shared__ uint32_t dynsm[];

__device__ __forceinline__ void gemm_core(const uint16_t* __restrict__ Agh,
                                          const uint16_t* __restrict__ Agl,
                                          const uint16_t* __restrict__ Bgh,
                                          const uint16_t* __restrict__ Bgl,
                                          float acc[4][4][4])
{
    const int tid  = threadIdx.x;
    const int lane = tid & 31;
    const int w    = tid >> 5;
    const int wm   = w >> 2, wn = w & 3;
    const int bm   = blockIdx.y, bn = blockIdx.x;
    const uint32_t smb = (uint32_t)__cvta_generic_to_shared(dynsm);

#pragma unroll
    for (int i = 0; i < 4; i++)
#pragma unroll
        for (int j = 0; j < 4; j++)
#pragma unroll
            for (int e = 0; e < 4; e++) acc[i][j][e] = 0.f;

    const int c0row = (2*tid) >> 2, c0off = (2*tid) & 3;
    const int c1row = (2*tid+1) >> 2, c1off = (2*tid+1) & 3;
    const size_t gA0 = (size_t)(bm*128 + c0row) * DM + c0off*8;
    const size_t gA1 = (size_t)(bm*128 + c1row) * DM + c1off*8;
    const size_t gB0 = (size_t)(bn*128 + c0row) * DM + c0off*8;
    const size_t gB1 = (size_t)(bn*128 + c1row) * DM + c1off*8;
    const int s0 = c0row*G_ST*4 + c0off*16;
    const int s1 = c1row*G_ST*4 + c1off*16;

    const int lrow  = (lane & 7) + ((lane >> 3) & 1) * 8;
    const int lcA   = ((lane >> 4) & 1) * 4;
    const int lrowB = (lane & 7) + ((lane >> 4) & 1) * 8;
    const int lcB   = ((lane >> 3) & 1) * 4;
    int aoff[4], boff[2];
#pragma unroll
    for (int mt = 0; mt < 4; mt++) aoff[mt] = (wm*64 + mt*16 + lrow) * G_ST + lcA;
#pragma unroll
    for (int np = 0; np < 2; np++) boff[np] = (wn*32 + np*16 + lrowB) * G_ST + lcB;

#define G_PREF(s, k0)                                                          \
    do {                                                                       \
        cpa16(smb + G_OFF(s,0)*4 + s0, Agh + gA0 + (k0));                      \
        cpa16(smb + G_OFF(s,0)*4 + s1, Agh + gA1 + (k0));                      \
        cpa16(smb + G_OFF(s,1)*4 + s0, Agl + gA0 + (k0));                      \
        cpa16(smb + G_OFF(s,1)*4 + s1, Agl + gA1 + (k0));                      \
        cpa16(smb + G_OFF(s,2)*4 + s0, Bgh + gB0 + (k0));                      \
        cpa16(smb + G_OFF(s,2)*4 + s1, Bgh + gB1 + (k0));                      \
        cpa16(smb + G_OFF(s,3)*4 + s0, Bgl + gB0 + (k0));                      \
        cpa16(smb + G_OFF(s,3)*4 + s1, Bgl + gB1 + (k0));                      \
        CPCOMMIT;                                                              \
    } while (0)

    G_PREF(0, 0);

    int buf = 0;
    for (int kt = 0; kt < 32; kt++){
        if (kt < 31){
            G_PREF(buf ^ 1, (kt + 1) * 32);
            cpwait<1>();
        } else {
            cpwait<0>();
        }
        __syncthreads();

        const int ah = G_OFF(buf,0), al = G_OFF(buf,1);
        const int bh = G_OFF(buf,2), bl = G_OFF(buf,3);
#pragma unroll
        for (int ks = 0; ks < 2; ks++){
            uint32_t Af[4][4], Alf[4][4], Bf[2][4], Blf[2][4];
#pragma unroll
            for (int mt = 0; mt < 4; mt++){
                ldsm4(Af[mt],  smb + (ah + aoff[mt] + ks*8)*4);
                ldsm4(Alf[mt], smb + (al + aoff[mt] + ks*8)*4);
            }
#pragma unroll
            for (int np = 0; np < 2; np++){
                ldsm4(Bf[np],  smb + (bh + boff[np] + ks*8)*4);
                ldsm4(Blf[np], smb + (bl + boff[np] + ks*8)*4);
            }
#pragma unroll
            for (int mt = 0; mt < 4; mt++)
#pragma unroll
                for (int nt = 0; nt < 4; nt++){
                    const uint32_t* bhp = &Bf [nt>>1][(nt&1)*2];
                    const uint32_t* blp = &Blf[nt>>1][(nt&1)*2];
                    mma16(acc[mt][nt], Af[mt],  bhp);
                    mma16(acc[mt][nt], Af[mt],  blp);
                    mma16(acc[mt][nt], Alf[mt], bhp);
                }
        }
        __syncthreads();
        buf ^= 1;
    }
#undef G_PREF
}

__global__ __launch_bounds__(256)
void gemm_qkv_kernel(){
    float acc[4][4][4];
    const int z = blockIdx.z;
    gemm_core(g_Xh, g_Xl, g_Wth + (size_t)z*DM*DM, g_Wtl + (size_t)z*DM*DM, acc);

    const int tid = threadIdx.x, lane = tid & 31, w = tid >> 5;
    const int g = lane >> 2, t = lane & 3, wm = w >> 2, wn = w & 3;
#pragma unroll
    for (int mt = 0; mt < 4; mt++){
        int r = blockIdx.y*128 + wm*64 + mt*16 + g;
#pragma unroll
        for (int nt = 0; nt < 4; nt++){
            int c = blockIdx.x*128 + wn*32 + nt*8 + 2*t;
            float v0 = acc[mt][nt][0], v1 = acc[mt][nt][1];
            float v2 = acc[mt][nt][2], v3 = acc[mt][nt][3];
            if (z == 2){
                *(float2*)(g_V + (size_t)r*DM + c)     = make_float2(v0, v1);
                *(float2*)(g_V + (size_t)(r+8)*DM + c) = make_float2(v2, v3);
            } else {
                // Q pre-scaled by (1/sqrt(64)) * log2(e) so softmax runs in base-2
                float sc = (z == 0) ? 0.18033688011112042f : 1.0f;
                uint32_t* dst = (z == 0) ? g_Qf : g_Kf;
                *(uint2*)(dst + (size_t)r*DM + c)     = make_uint2(f2tf(v0*sc), f2tf(v1*sc));
                *(uint2*)(dst + (size_t)(r+8)*DM + c) = make_uint2(f2tf(v2*sc), f2tf(v3*sc));
            }
        }
    }
}

__global__ __launch_bounds__(256)
void gemm_wo_kernel(float* __restrict__ out){
    float acc[4][4][4];
    gemm_core(g_Ah, g_Al, g_Wth + (size_t)3*DM*DM, g_Wtl + (size_t)3*DM*DM, acc);

    const int tid = threadIdx.x, lane = tid & 31, w = tid >> 5;
    const int g = lane >> 2, t = lane & 3, wm = w >> 2, wn = w & 3;
#pragma unroll
    for (int mt = 0; mt < 4; mt++){
        int r = blockIdx.y*128 + wm*64 + mt*16 + g;
#pragma unroll
        for (int nt = 0; nt < 4; nt++){
            int c = blockIdx.x*128 + wn*32 + nt*8 + 2*t;
            *(float2*)(out + (size_t)r*DM + c)     = make_float2(acc[mt][nt][0], acc[mt][nt][1]);
            *(float2*)(out + (size_t)(r+8)*DM + c) = make_float2(acc[mt][nt][2], acc[mt][nt][3]);
        }
    }
}

// ---------------- attention: QK tf32, PV bf16x3, kv-tile 64 ------------------
// K tile (tf32): 64 rows x 68 words, 2 buf. V^T tile (bf16 h+l): 64 x 36 words, 2 buf.
// Q (tf32) 128 x 68 overlaid by P (bf16, 16x36 hi + 16x36 lo per warp).
#define A_KBUF 4352
#define A_OK(b)  ((b)*A_KBUF)
#define A_VBUF 4608
#define A_OVH(b) (8704 + (b)*A_VBUF)
#define A_OVL(b) (A_OVH(b) + 2304)
#define A_OPQ    17920
#define A_SMEM_BYTES ((A_OPQ + 9216)*4)

__global__ __launch_bounds__(256)
void attn_kernel(){
    uint32_t* sm = dynsm;
    const uint32_t smb = (uint32_t)__cvta_generic_to_shared(sm);
    const int tid = threadIdx.x, lane = tid & 31, w = tid >> 5;
    const int g = lane >> 2, t = lane & 3;
    const int h = blockIdx.y;
    const int q0 = blockIdx.x * 128;

    const int lrow  = (lane & 7) + ((lane >> 3) & 1) * 8;
    const int lcA   = ((lane >> 4) & 1) * 4;
    const int lrowB = (lane & 7) + ((lane >> 4) & 1) * 8;
    const int lcB   = ((lane >> 3) & 1) * 4;

#define A_PREF_KV(b, j0)                                                          \
    do {                                                                          \
        _Pragma("unroll")                                                         \
        for (int i = 0; i < 4; i++){                                              \
            int row = tid >> 2; int colw = (tid & 3)*4 + i*16;                    \
            cpa16(smb + (A_OK(b) + row*68 + colw)*4,                              \
                  g_Kf + (size_t)((j0)+row)*DM + (size_t)h*64 + colw);            \
        }                                                                         \
        _Pragma("unroll")                                                         \
        for (int i = 0; i < 2; i++){                                              \
            int row = (tid >> 3) + i*32; int cw = (tid & 7)*4;                    \
            cpa16(smb + (A_OVH(b) + row*36 + cw)*4,                               \
                  g_Vth + (size_t)(h*64+row)*SEQ + (j0) + cw*2);                  \
            cpa16(smb + (A_OVL(b) + row*36 + cw)*4,                               \
                  g_Vtl + (size_t)(h*64+row)*SEQ + (j0) + cw*2);                  \
        }                                                                         \
        CPCOMMIT;                                                                 \
    } while (0)

    const int ntile = blockIdx.x * 2 + 2;

    // prologue: KV tile 0 + Q
    A_PREF_KV(0, 0);
#pragma unroll
    for (int i = 0; i < 8; i++){
        int c = tid + i*256;
        int qr = c >> 4, qc = (c & 15) * 4;
        cpa16(smb + (A_OPQ + qr*68 + qc)*4, g_Qf + (size_t)(q0+qr)*DM + (size_t)h*64 + qc);
    }
    CPCOMMIT;
    cpwait<0>();
    __syncthreads();

    uint32_t qf[8][4];
#pragma unroll
    for (int kcc = 0; kcc < 8; kcc++)
        ldsm4(qf[kcc], smb + (A_OPQ + (w*16 + lrow)*68 + kcc*8 + lcA)*4);
    __syncthreads();       // Q region becomes P region

    float o[8][4];
#pragma unroll
    for (int nd = 0; nd < 8; nd++)
#pragma unroll
        for (int e = 0; e < 4; e++) o[nd][e] = 0.f;
    float m0 = -1e30f, m1 = -1e30f, l0 = 0.f, l1 = 0.f;

    const int r0 = q0 + w*16 + g, r1 = r0 + 8;
    uint32_t* Ph = sm + A_OPQ + w * 1152;
    uint32_t* Pl = Ph + 576;
    const uint32_t phb = smb + (A_OPQ + w*1152)*4;
    const uint32_t plb = phb + 576*4;

    int buf = 0;
    for (int it = 0; it < ntile; it++){
        if (it + 1 < ntile){
            A_PREF_KV(buf ^ 1, (it + 1) * 64);
            cpwait<1>();
        } else {
            cpwait<0>();
        }
        __syncthreads();

        // S = Q K^T (tf32), 64 keys
        float s[8][4];
#pragma unroll
        for (int nt = 0; nt < 8; nt++)
#pragma unroll
            for (int e = 0; e < 4; e++) s[nt][e] = 0.f;
#pragma unroll
        for (int kcc = 0; kcc < 8; kcc++){
            uint32_t Bf[4][4];
#pragma unroll
            for (int np = 0; np < 4; np++)
                ldsm4(Bf[np], smb + (A_OK(buf) + (np*16+lrowB)*68 + kcc*8 + lcB)*4);
#pragma unroll
            for (int nt = 0; nt < 8; nt++)
                mma8(s[nt], qf[kcc], &Bf[nt>>1][(nt&1)*2]);
        }

        const int j0 = it * 64;
        const bool domask = (j0 >= q0);

        float mx0 = -1e30f, mx1 = -1e30f;
#pragma unroll
        for (int nt = 0; nt < 8; nt++){
            int jc = j0 + nt*8 + 2*t;
#pragma unroll
            for (int e = 0; e < 4; e++){
                int j = jc + (e & 1);
                int r = (e < 2) ? r0 : r1;
                float sc = s[nt][e];
                if (domask && j > r) sc = -1e30f;
                s[nt][e] = sc;
                if (e < 2) mx0 = fmaxf(mx0, sc); else mx1 = fmaxf(mx1, sc);
            }
        }
        mx0 = fmaxf(mx0, __shfl_xor_sync(0xffffffffu, mx0, 1));
        mx0 = fmaxf(mx0, __shfl_xor_sync(0xffffffffu, mx0, 2));
        mx1 = fmaxf(mx1, __shfl_xor_sync(0xffffffffu, mx1, 1));
        mx1 = fmaxf(mx1, __shfl_xor_sync(0xffffffffu, mx1, 2));

        float mn0 = fmaxf(m0, mx0), mn1 = fmaxf(m1, mx1);
        bool nochange = (mn0 == m0) && (mn1 == m1);
        if (!__all_sync(0xffffffffu, nochange)){
            float a0 = ex2(m0 - mn0), a1 = ex2(m1 - mn1);
            m0 = mn0; m1 = mn1;
            l0 *= a0;  l1 *= a1;
#pragma unroll
            for (int nd = 0; nd < 8; nd++){
                o[nd][0] *= a0; o[nd][1] *= a0;
                o[nd][2] *= a1; o[nd][3] *= a1;
            }
        }

        // p = 2^(s-m), split to bf16 hi/lo, store packed pairs
#pragma unroll
        for (int nt = 0; nt < 8; nt++){
            float p0 = ex2(s[nt][0] - mn0), p1 = ex2(s[nt][1] - mn0);
            float p2 = ex2(s[nt][2] - mn1), p3 = ex2(s[nt][3] - mn1);
            l0 += p0 + p1; l1 += p2 + p3;
            uint16_t h0,lo0,h1,lo1,h2,lo2,h3,lo3;
            split2b(p0,h0,lo0); split2b(p1,h1,lo1);
            split2b(p2,h2,lo2); split2b(p3,h3,lo3);
            int pw = nt*4 + t;
            Ph[g*36 + pw]     = (uint32_t)h0  | ((uint32_t)h1  << 16);
            Ph[(g+8)*36 + pw] = (uint32_t)h2  | ((uint32_t)h3  << 16);
            Pl[g*36 + pw]     = (uint32_t)lo0 | ((uint32_t)lo1 << 16);
            Pl[(g+8)*36 + pw] = (uint32_t)lo2 | ((uint32_t)lo3 << 16);
        }
        __syncwarp();

        // O += P V  (bf16x3, k16, 64 keys = 4 k-chunks)
#pragma unroll
        for (int kt = 0; kt < 4; kt++){
            uint32_t pf[4], plf[4];
            ldsm4(pf,  phb + (lrow*36 + kt*8 + lcA)*4);
            ldsm4(plf, plb + (lrow*36 + kt*8 + lcA)*4);
#pragma unroll
            for (int np = 0; np < 4; np++){
                uint32_t Vf[4], Vlf[4];
                ldsm4(Vf,  smb + (A_OVH(buf) + (np*16+lrowB)*36 + kt*8 + lcB)*4);
                ldsm4(Vlf, smb + (A_OVL(buf) + (np*16+lrowB)*36 + kt*8 + lcB)*4);
                mma16(o[2*np],   pf,  &Vf[0]);
                mma16(o[2*np],   pf,  &Vlf[0]);
                mma16(o[2*np],   plf, &Vf[0]);
                mma16(o[2*np+1], pf,  &Vf[2]);
                mma16(o[2*np+1], pf,  &Vlf[2]);
                mma16(o[2*np+1], plf, &Vf[2]);
            }
        }
        __syncthreads();
        buf ^= 1;
    }
#undef A_PREF_KV

    l0 += __shfl_xor_sync(0xffffffffu, l0, 1);
    l0 += __shfl_xor_sync(0xffffffffu, l0, 2);
    l1 += __shfl_xor_sync(0xffffffffu, l1, 1);
    l1 += __shfl_xor_sync(0xffffffffu, l1, 2);
    float inv0 = 1.f / l0, inv1 = 1.f / l1;

#pragma unroll
    for (int nd = 0; nd < 8; nd++){
        int c = h*64 + nd*8 + 2*t;
        uint16_t h0,lo0,h1,lo1;
        split2b(o[nd][0]*inv0, h0, lo0); split2b(o[nd][1]*inv0, h1, lo1);
        ((uint32_t*)g_Ah)[((size_t)r0*DM + c) >> 1] = (uint32_t)h0  | ((uint32_t)h1 << 16);
        ((uint32_t*)g_Al)[((size_t)r0*DM + c) >> 1] = (uint32_t)lo0 | ((uint32_t)lo1 << 16);
        split2b(o[nd][2]*inv1, h0, lo0); split2b(o[nd][3]*inv1, h1, lo1);
        ((uint32_t*)g_Ah)[((size_t)r1*DM + c) >> 1] = (uint32_t)h0  | ((uint32_t)h1 << 16);
        ((uint32_t*)g_Al)[((size_t)r1*DM + c) >> 1] = (uint32_t)lo0 | ((uint32_t)lo1 << 16);
    }
}

// ---------------- launch ----------------
extern "C" void kernel_launch(void* const* d_in, const int* in_sizes, int n_in,
                              void* d_out, int out_size)
{
    const float* x  = (const float*)d_in[0];
    const float* Wq = (const float*)d_in[1];
    const float* Wk = (const float*)d_in[2];
    const float* Wv = (const float*)d_in[3];
    const float* Wo = (const float*)d_in[4];
    float* out = (float*)d_out;

    cudaFuncSetAttribute(gemm_qkv_kernel, cudaFuncAttributeMaxDynamicSharedMemorySize, G_SMEM_BYTES);
    cudaFuncSetAttribute(gemm_wo_kernel,  cudaFuncAttributeMaxDynamicSharedMemorySize, G_SMEM_BYTES);
    cudaFuncSetAttribute(attn_kernel,     cudaFuncAttributeMaxDynamicSharedMemorySize, A_SMEM_BYTES);

    split_x_kernel<<<SEQ*DM/1024, 256>>>(x);
    splitT_w_kernel<<<dim3(32,32,4), dim3(32,8)>>>(Wq, Wk, Wv, Wo);

    gemm_qkv_kernel<<<dim3(8,32,3), 256, G_SMEM_BYTES>>>();

    vsplitT_kernel<<<dim3(32,128), dim3(32,8)>>>();

    attn_kernel<<<dim3(32,16), 256, A_SMEM_BYTES>>>();

    gemm_wo_kernel<<<dim3(8,32), 256, G_SMEM_BYTES>>>(out);
}